// round 13
// baseline (speedup 1.0000x reference)
#include <cuda_runtime.h>

#define B_   256
#define T_   256
#define Cp1  129
#define H_   128
#define G3   384
#define TT   32
#define TTPAD 36

// Scratch (static __device__ arrays — no runtime allocation)
__device__ float g_gi[(size_t)B_ * T_ * G3];     // (B, T, 3H) GRU1 input proj incl. bih1 (+bhh1 r/z)
__device__ float g_out1[(size_t)B_ * T_ * H_];   // (B, T, H) zero-padded GRU1 output
__device__ float g_WihT[Cp1 * G3];               // transposed Wih1: [k][g]
__device__ float g_WfcT[Cp1 * H_];               // transposed Wfc:  [k][c]
__device__ float g_s[(size_t)T_ * 6 * B_];       // GRU2 input projections: [t][gate][b]

typedef unsigned long long u64;

__device__ __forceinline__ u64 pack2(float lo, float hi) {
    u64 r;
    asm("mov.b64 %0, {%1, %2};" : "=l"(r) : "r"(__float_as_uint(lo)), "r"(__float_as_uint(hi)));
    return r;
}
__device__ __forceinline__ void unpack2(u64 v, float& lo, float& hi) {
    unsigned int a, b;
    asm("mov.b64 {%0, %1}, %2;" : "=r"(a), "=r"(b) : "l"(v));
    lo = __uint_as_float(a); hi = __uint_as_float(b);
}
__device__ __forceinline__ u64 fma2(u64 a, u64 b, u64 c) {
    u64 d;
    asm("fma.rn.f32x2 %0, %1, %2, %3;" : "=l"(d) : "l"(a), "l"(b), "l"(c));
    return d;
}
// Fast activations: MUFU-based, rel err ~1e-6 (threshold is 1e-3).
__device__ __forceinline__ float sigm(float v) {
    return __fdividef(1.0f, 1.0f + __expf(-v));
}
__device__ __forceinline__ float tanh_fast(float x) {
    float t = __expf(-2.0f * fabsf(x));            // in (0, 1]: overflow-safe
    float r = (1.0f - t) * __fdividef(1.0f, 1.0f + t);
    return copysignf(r, x);
}

// ---------------------------------------------------------------------------
// K0: one-off weight transposes so K1/K3 weight loads are fully coalesced.
// ---------------------------------------------------------------------------
__global__ void k0_transpose(const float* __restrict__ Wih1, const float* __restrict__ Wfc) {
    int idx = blockIdx.x * 256 + threadIdx.x;
    if (idx < Cp1 * G3) {
        int k = idx / G3, g = idx - k * G3;
        g_WihT[idx] = Wih1[(size_t)g * Cp1 + k];
    }
    if (idx < Cp1 * H_) {
        int k = idx / H_, c = idx - k * H_;
        g_WfcT[idx] = Wfc[(size_t)c * Cp1 + k];
    }
}

// ---------------------------------------------------------------------------
// K1: gi[b,t,g] = bih1[g] (+ bhh1[g] for r/z gates) + sum_d x[b,t,d]*Wih1[g,d]
// (tiles with t0 < len[b]). r/z hidden biases fold here (additive pre-sigmoid),
// off K2's serial critical path; n-gate bias stays in K2 (multiplied by r).
// Also writes lengths (as float) to the output tail.
// grid (8, 256), block 128. Thread: rows (tid, tid+128, tid+256), 32 t.
// x pairs via LDS.128 (ulonglong2): two f32x2 operands per load, no MOVs.
// ---------------------------------------------------------------------------
__global__ void k1_gi(const float* __restrict__ x, const int* __restrict__ len,
                      const float* __restrict__ bih1, const float* __restrict__ bhh1,
                      float* __restrict__ olen) {
    int b = blockIdx.y, t0 = blockIdx.x * TT, tid = threadIdx.x;
    int L = len[b];
    if (blockIdx.x == 0 && tid == 0) olen[b] = (float)L;
    if (t0 >= L) return;

    __shared__ __align__(16) float xs[Cp1 * TTPAD];   // [k][tt], tt-stride padded to 36 (144B: 16B-aligned rows)
    {
        int w = tid >> 5, l = tid & 31;
        for (int tt = w; tt < TT; tt += 4) {
            const float* xrow = x + ((size_t)b * T_ + t0 + tt) * Cp1;
            for (int k = l; k < Cp1; k += 32) xs[k * TTPAD + tt] = xrow[k];
        }
    }
    __syncthreads();

    int g0 = tid, g1 = tid + 128, g2 = tid + 256;
    float bb0 = bih1[g0] + bhh1[g0];   // r gate: fold hidden bias
    float bb1 = bih1[g1] + bhh1[g1];   // z gate: fold hidden bias
    float bb2 = bih1[g2];              // n gate: hidden bias stays in K2

    u64 a0[16], a1[16], a2[16];
#pragma unroll
    for (int j = 0; j < 16; j++) { a0[j] = pack2(bb0, bb0); a1[j] = pack2(bb1, bb1); a2[j] = pack2(bb2, bb2); }

    const float* WT = g_WihT;
    for (int k = 0; k < Cp1; k++) {
        float w0 = __ldg(WT + k * G3 + g0);
        float w1 = __ldg(WT + k * G3 + g1);
        float w2 = __ldg(WT + k * G3 + g2);
        u64 w0p = pack2(w0, w0), w1p = pack2(w1, w1), w2p = pack2(w2, w2);
        const ulonglong2* xs16 = (const ulonglong2*)(xs + k * TTPAD);
#pragma unroll
        for (int j = 0; j < 8; j++) {
            ulonglong2 xv = xs16[j];
            a0[2 * j]     = fma2(w0p, xv.x, a0[2 * j]);
            a1[2 * j]     = fma2(w1p, xv.x, a1[2 * j]);
            a2[2 * j]     = fma2(w2p, xv.x, a2[2 * j]);
            a0[2 * j + 1] = fma2(w0p, xv.y, a0[2 * j + 1]);
            a1[2 * j + 1] = fma2(w1p, xv.y, a1[2 * j + 1]);
            a2[2 * j + 1] = fma2(w2p, xv.y, a2[2 * j + 1]);
        }
    }

    size_t base = ((size_t)b * T_ + t0) * G3;
#pragma unroll
    for (int j = 0; j < 16; j++) {
        float lo, hi;
        unpack2(a0[j], lo, hi);
        g_gi[base + (size_t)(2 * j) * G3 + g0] = lo;
        g_gi[base + (size_t)(2 * j + 1) * G3 + g0] = hi;
        unpack2(a1[j], lo, hi);
        g_gi[base + (size_t)(2 * j) * G3 + g1] = lo;
        g_gi[base + (size_t)(2 * j + 1) * G3 + g1] = hi;
        unpack2(a2[j], lo, hi);
        g_gi[base + (size_t)(2 * j) * G3 + g2] = lo;
        g_gi[base + (size_t)(2 * j + 1) * G3 + g2] = hi;
    }
}

// ---------------------------------------------------------------------------
// K2: GRU1 recurrence ONLY (GRU2 in K2s + K2c).
// grid 128, block 512. CTA g handles batches g and 255-g (length-balanced).
// Warp w owns rows i = 8w..8w+7; lane quad c = lane&3 owns k-chunk [32c,32c+32).
// Whh1 register-resident as f32x2 pairs (96 regs/thread). Single accumulator
// per gate (issue-bound; 3 gate chains give ILP 3) keeps regs under the 128
// cap at 512 threads. h operands via LDS.128 (8 loads/step).
// Strength-reduced incrementing pointers for gi prefetch (gp, saturating at
// row L-1) and out1 store (op). Quad reduction via 2 shfl.bfly; finalize on
// lane%4==0; hs double-buffered -> ONE barrier/step.
// ---------------------------------------------------------------------------
__global__ void __launch_bounds__(512, 1) k2_rnn(
    const int* __restrict__ len, const float* __restrict__ h01,
    const float* __restrict__ Whh1, const float* __restrict__ bhh1) {
    __shared__ __align__(16) float hs[2][H_];

    int tid  = threadIdx.x;
    int lane = tid & 31;
    int warp = tid >> 5;
    int i    = warp * 8 + (lane >> 2);   // row (0..127)
    int c    = lane & 3;                  // k-chunk
    bool fin = (c == 0);

    // Register-resident Whh1 (packed k-pairs): rows {i, 128+i, 256+i}, k in [32c,32c+32)
    u64 wr[16], wz[16], wn[16];
    {
        const float2* W2 = (const float2*)Whh1;
        int rr = i * 64 + c * 16;
        int rz = (128 + i) * 64 + c * 16;
        int rn = (256 + i) * 64 + c * 16;
#pragma unroll
        for (int j = 0; j < 16; j++) {
            float2 a = W2[rr + j]; wr[j] = pack2(a.x, a.y);
            float2 bz2 = W2[rz + j]; wz[j] = pack2(bz2.x, bz2.y);
            float2 bn2 = W2[rn + j]; wn[j] = pack2(bn2.x, bn2.y);
        }
    }
    float bn = bhh1[256 + i];   // only the n-gate hidden bias survives into K2

    for (int half = 0; half < 2; half++) {
        int b = half ? (255 - (int)blockIdx.x) : (int)blockIdx.x;
        int L = len[b];

        float hcur = 0.f;
        if (fin) { hcur = h01[b * H_ + i]; hs[0][i] = hcur; }

        // Incrementing pointers: gp -> gi row of the *next* prefetch (clamped
        // at L-1); op -> out1 row t. Increments run in all lanes (cheap);
        // loads/stores stay fin-predicated.
        const float* gp = g_gi + (size_t)b * T_ * G3 + i;
        float*       op = g_out1 + (size_t)b * T_ * H_ + i;

        float gr = 0.f, gz = 0.f, gn = 0.f;
        if (fin) { gr = gp[0]; gz = gp[128]; gn = gp[256]; }
        __syncthreads();

        for (int t = 0; t < L; t++) {
            const float* hb = hs[t & 1];

            // matvec partials over k-chunk c — LDS.128 h operands
            u64 Z = pack2(0.f, 0.f);
            u64 ar = Z, az = Z, an = Z;
            const ulonglong2* hb16 = (const ulonglong2*)(hb + c * 32);
#pragma unroll
            for (int j = 0; j < 8; j++) {
                ulonglong2 hv = hb16[j];
                ar = fma2(wr[2 * j], hv.x, ar);
                az = fma2(wz[2 * j], hv.x, az);
                an = fma2(wn[2 * j], hv.x, an);
                ar = fma2(wr[2 * j + 1], hv.y, ar);
                az = fma2(wz[2 * j + 1], hv.y, az);
                an = fma2(wn[2 * j + 1], hv.y, an);
            }

            // advance prefetch row (saturating at L-1), prefetch next gi
            gp += (t + 1 < L) ? G3 : 0;
            float grn = 0.f, gzn = 0.f, gnn = 0.f;
            if (fin) { grn = gp[0]; gzn = gp[128]; gnn = gp[256]; }

            // horizontal + quad reduction
            float sr, sz, sn;
            {
                float lo, hi;
                unpack2(ar, lo, hi); sr = lo + hi;
                unpack2(az, lo, hi); sz = lo + hi;
                unpack2(an, lo, hi); sn = lo + hi;
            }
            sr += __shfl_xor_sync(0xffffffffu, sr, 1);
            sz += __shfl_xor_sync(0xffffffffu, sz, 1);
            sn += __shfl_xor_sync(0xffffffffu, sn, 1);
            sr += __shfl_xor_sync(0xffffffffu, sr, 2);
            sz += __shfl_xor_sync(0xffffffffu, sz, 2);
            sn += __shfl_xor_sync(0xffffffffu, sn, 2);

            if (fin) {
                float r = sigm(gr + sr);               // biases pre-folded in K1
                float z = sigm(gz + sz);
                float n = tanh_fast(gn + r * (bn + sn));
                hcur = (1.0f - z) * n + z * hcur;
                hs[(t + 1) & 1][i] = hcur;
                *op = hcur;
                gr = grn; gz = gzn; gn = gnn;
            }
            op += H_;
            __syncthreads();
        }

        // zero-pad out1 tail
        {
            size_t obase = ((size_t)b * T_ + L) * H_;
            int cnt = (T_ - L) * H_;
            for (int idx = tid; idx < cnt; idx += 512) g_out1[obase + idx] = 0.f;
        }
        __syncthreads();
    }
}

// ---------------------------------------------------------------------------
// K2s: GRU2 input projections s[t][g][b] = bih2[g] + sum_k h1[b,t,k]*Wih2[g,k].
// grid (8, 256) = (b-tile 32, t), block 192 = 6 gates x 32 b.
// hsm stride 129 -> conflict-free (bank = (b+k)%32). Wih2 reads broadcast.
// Lengths sorted desc: t >= len[b0] means whole tile masked.
// ---------------------------------------------------------------------------
__global__ void k2s_proj(const int* __restrict__ len,
                         const float* __restrict__ Wih2, const float* __restrict__ bih2) {
    int b0 = blockIdx.x * 32, t = blockIdx.y, tid = threadIdx.x;
    if (t >= len[b0]) return;

    __shared__ float hsm[32 * 129];
    for (int idx = tid; idx < 32 * H_; idx += 192) {
        int row = idx >> 7, k = idx & 127;
        hsm[row * 129 + k] = g_out1[((size_t)(b0 + row) * T_ + t) * H_ + k];
    }
    __syncthreads();

    int g = tid / 32, bb = tid & 31;
    float acc = bih2[g];
    const float* Wg = Wih2 + g * H_;
    const float* hr = hsm + bb * 129;
#pragma unroll 8
    for (int k = 0; k < H_; k++) acc += __ldg(Wg + k) * hr[k];
    g_s[(size_t)t * (6 * B_) + g * B_ + b0 + bb] = acc;
}

// ---------------------------------------------------------------------------
// K2c: GRU2 P=2 recurrence + params = exp(-h2). One lane per batch,
// grid 8 x 32 threads, no barriers, 3-deep s-prefetch hides L2 latency.
// Tail t >= L: params = exp(-0) = 1.
// ---------------------------------------------------------------------------
__global__ void k2c_scan(const int* __restrict__ len, const float* __restrict__ h02,
                         const float* __restrict__ Whh2, const float* __restrict__ bhh2,
                         float* __restrict__ params) {
    int b = blockIdx.x * 32 + threadIdx.x;
    int L = len[b];
    float h2a = h02[b * 2], h2b = h02[b * 2 + 1];
    float wq[12], bq[6];
#pragma unroll
    for (int q = 0; q < 12; q++) wq[q] = Whh2[q];
#pragma unroll
    for (int q = 0; q < 6; q++) bq[q] = bhh2[q];

    const float* S = g_s;
    float s0[6], s1[6], s2[6];
#pragma unroll
    for (int g = 0; g < 6; g++) s0[g] = S[(size_t)0 * (6 * B_) + g * B_ + b];
    int t1 = (1 < L) ? 1 : L - 1;
#pragma unroll
    for (int g = 0; g < 6; g++) s1[g] = S[(size_t)t1 * (6 * B_) + g * B_ + b];
    int t2 = (2 < L) ? 2 : L - 1;
#pragma unroll
    for (int g = 0; g < 6; g++) s2[g] = S[(size_t)t2 * (6 * B_) + g * B_ + b];

    for (int t = 0; t < L; t++) {
        float gh[6];
#pragma unroll
        for (int q = 0; q < 6; q++) gh[q] = bq[q] + wq[2 * q] * h2a + wq[2 * q + 1] * h2b;
        float r0 = sigm(s0[0] + gh[0]);
        float r1 = sigm(s0[1] + gh[1]);
        float z0 = sigm(s0[2] + gh[2]);
        float z1 = sigm(s0[3] + gh[3]);
        float n0 = tanh_fast(s0[4] + r0 * gh[4]);
        float n1 = tanh_fast(s0[5] + r1 * gh[5]);
        h2a = (1.0f - z0) * n0 + z0 * h2a;
        h2b = (1.0f - z1) * n1 + z1 * h2b;
        size_t o = ((size_t)b * T_ + t) * 2;
        params[o]     = __expf(-h2a);
        params[o + 1] = __expf(-h2b);

        // rotate pipeline, prefetch t+3
#pragma unroll
        for (int g = 0; g < 6; g++) { s0[g] = s1[g]; s1[g] = s2[g]; }
        int tn = (t + 3 < L) ? t + 3 : L - 1;
#pragma unroll
        for (int g = 0; g < 6; g++) s2[g] = S[(size_t)tn * (6 * B_) + g * B_ + b];
    }
    for (int t = L; t < T_; t++) {
        size_t o = ((size_t)b * T_ + t) * 2;
        params[o] = 1.0f;
        params[o + 1] = 1.0f;
    }
}

// ---------------------------------------------------------------------------
// K3: preds[b,t,c] = bfc[c] + sum_{k<128} out1[b,t,k]*Wfc[c,k] + x[b,t,0]*Wfc[c,128]
// for t < len[b]-1 (and t < 255); 0 elsewhere. grid (8, 256), block 128.
// h operands via LDS.128 (ulonglong2).
// ---------------------------------------------------------------------------
__global__ void k3_fc(const float* __restrict__ x, const int* __restrict__ len,
                      const float* __restrict__ bfc, float* __restrict__ preds) {
    int b = blockIdx.y, t0 = blockIdx.x * TT, tid = threadIdx.x;
    int L1 = len[b] - 1;

    if (t0 >= L1) {  // fully masked tile: write exact zeros (d_out is poisoned)
        for (int tt = 0; tt < TT; tt++) {
            int t = t0 + tt;
            if (t >= T_ - 1) break;
            preds[((size_t)b * (T_ - 1) + t) * H_ + tid] = 0.f;
        }
        return;
    }

    __shared__ __align__(16) float hsm[Cp1 * TTPAD];   // [k][tt], k=128 is time feature
    {
        int w = tid >> 5, l = tid & 31;
        for (int tt = w; tt < TT; tt += 4) {
            int t = t0 + tt;
            const float* hr = g_out1 + ((size_t)b * T_ + t) * H_;
            for (int k = l; k < H_; k += 32) hsm[k * TTPAD + tt] = hr[k];
            if (l == 0) hsm[128 * TTPAD + tt] = x[((size_t)b * T_ + t) * Cp1];
        }
    }
    __syncthreads();

    float bb = bfc[tid];
    u64 acc[16];
#pragma unroll
    for (int j = 0; j < 16; j++) acc[j] = pack2(bb, bb);

    const float* WT = g_WfcT;
    for (int k = 0; k < Cp1; k++) {
        float w = __ldg(WT + k * H_ + tid);
        u64 wp = pack2(w, w);
        const ulonglong2* hs16 = (const ulonglong2*)(hsm + k * TTPAD);
#pragma unroll
        for (int j = 0; j < 8; j++) {
            ulonglong2 hv = hs16[j];
            acc[2 * j]     = fma2(wp, hv.x, acc[2 * j]);
            acc[2 * j + 1] = fma2(wp, hv.y, acc[2 * j + 1]);
        }
    }

#pragma unroll
    for (int j = 0; j < 16; j++) {
        float lo, hi;
        unpack2(acc[j], lo, hi);
        int t = t0 + 2 * j;
        if (t < T_ - 1) preds[((size_t)b * (T_ - 1) + t) * H_ + tid] = (t < L1) ? lo : 0.f;
        t++;
        if (t < T_ - 1) preds[((size_t)b * (T_ - 1) + t) * H_ + tid] = (t < L1) ? hi : 0.f;
    }
}

// ---------------------------------------------------------------------------
extern "C" void kernel_launch(void* const* d_in, const int* in_sizes, int n_in,
                              void* d_out, int out_size) {
    const float* x    = (const float*)d_in[0];
    const int*   len  = (const int*)  d_in[1];
    const float* h01  = (const float*)d_in[2];
    const float* h02  = (const float*)d_in[3];
    const float* Wih1 = (const float*)d_in[4];
    const float* Whh1 = (const float*)d_in[5];
    const float* bih1 = (const float*)d_in[6];
    const float* bhh1 = (const float*)d_in[7];
    const float* Wih2 = (const float*)d_in[8];
    const float* Whh2 = (const float*)d_in[9];
    const float* bih2 = (const float*)d_in[10];
    const float* bhh2 = (const float*)d_in[11];
    const float* Wfc  = (const float*)d_in[12];
    const float* bfc  = (const float*)d_in[13];

    float* preds  = (float*)d_out;                              // (B, T-1, C) = 256*255*128
    float* params = preds + (size_t)B_ * (T_ - 1) * H_;         // (B, T, 2)
    float* olen   = params + (size_t)B_ * T_ * 2;               // (B,) lengths as float

    k0_transpose<<<(Cp1 * G3 + 255) / 256, 256>>>(Wih1, Wfc);
    k1_gi<<<dim3(8, B_), 128>>>(x, len, bih1, bhh1, olen);
    k2_rnn<<<128, 512>>>(len, h01, Whh1, bhh1);
    k2s_proj<<<dim3(8, T_), 192>>>(len, Wih2, bih2);
    k2c_scan<<<8, 32>>>(len, h02, Whh2, bhh2, params);
    k3_fc<<<dim3(8, B_), 128>>>(x, len, bfc, preds);
}

// round 14
// speedup vs baseline: 1.3601x; 1.3601x over previous
#include <cuda_runtime.h>

#define B_   256
#define T_   256
#define Cp1  129
#define H_   128
#define G3   384
#define TT   32
#define TTPAD 36
#define HCH  40   // padded h-chunk stride (floats) in K2: bank offset 8c -> conflict-free

// Scratch (static __device__ arrays — no runtime allocation)
__device__ float g_gi[(size_t)B_ * T_ * G3];     // (B, T, 3H) GRU1 input proj incl. bih1 (+bhh1 r/z)
__device__ float g_out1[(size_t)B_ * T_ * H_];   // (B, T, H) zero-padded GRU1 output
__device__ float g_WihT[Cp1 * G3];               // transposed Wih1: [k][g]
__device__ float g_WfcT[Cp1 * H_];               // transposed Wfc:  [k][c]
__device__ float g_s[(size_t)T_ * 6 * B_];       // GRU2 input projections: [t][gate][b]

typedef unsigned long long u64;

__device__ __forceinline__ u64 pack2(float lo, float hi) {
    u64 r;
    asm("mov.b64 %0, {%1, %2};" : "=l"(r) : "r"(__float_as_uint(lo)), "r"(__float_as_uint(hi)));
    return r;
}
__device__ __forceinline__ void unpack2(u64 v, float& lo, float& hi) {
    unsigned int a, b;
    asm("mov.b64 {%0, %1}, %2;" : "=r"(a), "=r"(b) : "l"(v));
    lo = __uint_as_float(a); hi = __uint_as_float(b);
}
__device__ __forceinline__ u64 fma2(u64 a, u64 b, u64 c) {
    u64 d;
    asm("fma.rn.f32x2 %0, %1, %2, %3;" : "=l"(d) : "l"(a), "l"(b), "l"(c));
    return d;
}
// Fast activations: MUFU-based, rel err ~1e-6 (measured total rel_err 2.9e-7, threshold 1e-3).
__device__ __forceinline__ float sigm(float v) {
    return __fdividef(1.0f, 1.0f + __expf(-v));
}
__device__ __forceinline__ float tanh_fast(float x) {
    float t = __expf(-2.0f * fabsf(x));            // in (0, 1]: overflow-safe
    float r = (1.0f - t) * __fdividef(1.0f, 1.0f + t);
    return copysignf(r, x);
}

// ---------------------------------------------------------------------------
// K0: one-off weight transposes so K1/K3 weight loads are fully coalesced.
// ---------------------------------------------------------------------------
__global__ void k0_transpose(const float* __restrict__ Wih1, const float* __restrict__ Wfc) {
    int idx = blockIdx.x * 256 + threadIdx.x;
    if (idx < Cp1 * G3) {
        int k = idx / G3, g = idx - k * G3;
        g_WihT[idx] = Wih1[(size_t)g * Cp1 + k];
    }
    if (idx < Cp1 * H_) {
        int k = idx / H_, c = idx - k * H_;
        g_WfcT[idx] = Wfc[(size_t)c * Cp1 + k];
    }
}

// ---------------------------------------------------------------------------
// K1: gi[b,t,g] = bih1[g] (+ bhh1[g] for r/z gates) + sum_d x[b,t,d]*Wih1[g,d].
// REDESIGNED for register safety: block 384, ONE gate-row per thread ->
// accumulators are 16 u64 = 32 regs (was 96). Total ~55 regs: provably no
// spills. Same total FMA issue; xs reads are pure broadcast (1 wavefront).
// grid (8, 256). Also writes lengths (as float) to the output tail.
// ---------------------------------------------------------------------------
__global__ void __launch_bounds__(384) k1_gi(
    const float* __restrict__ x, const int* __restrict__ len,
    const float* __restrict__ bih1, const float* __restrict__ bhh1,
    float* __restrict__ olen) {
    int b = blockIdx.y, t0 = blockIdx.x * TT, tid = threadIdx.x;
    int L = len[b];
    if (blockIdx.x == 0 && tid == 0) olen[b] = (float)L;
    if (t0 >= L) return;

    __shared__ __align__(16) float xs[Cp1 * TTPAD];   // [k][tt]
    {
        int w = tid >> 5, l = tid & 31;
        for (int tt = w; tt < TT; tt += 12) {
            const float* xrow = x + ((size_t)b * T_ + t0 + tt) * Cp1;
            for (int k = l; k < Cp1; k += 32) xs[k * TTPAD + tt] = xrow[k];
        }
    }
    __syncthreads();

    int g = tid;                                   // gate-row 0..383
    float bb = bih1[g] + ((g < 256) ? bhh1[g] : 0.0f);  // fold r/z hidden biases

    u64 a[16];
#pragma unroll
    for (int j = 0; j < 16; j++) a[j] = pack2(bb, bb);

    const float* WT = g_WihT;
    for (int k = 0; k < Cp1; k++) {
        float w = __ldg(WT + k * G3 + g);          // coalesced across 384 threads
        u64 wp = pack2(w, w);
        const ulonglong2* xs16 = (const ulonglong2*)(xs + k * TTPAD);  // broadcast
#pragma unroll
        for (int j = 0; j < 8; j++) {
            ulonglong2 xv = xs16[j];
            a[2 * j]     = fma2(wp, xv.x, a[2 * j]);
            a[2 * j + 1] = fma2(wp, xv.y, a[2 * j + 1]);
        }
    }

    size_t base = ((size_t)b * T_ + t0) * G3;
#pragma unroll
    for (int j = 0; j < 16; j++) {
        float lo, hi;
        unpack2(a[j], lo, hi);
        g_gi[base + (size_t)(2 * j) * G3 + g] = lo;
        g_gi[base + (size_t)(2 * j + 1) * G3 + g] = hi;
    }
}

// ---------------------------------------------------------------------------
// K2: GRU1 recurrence. grid 128, block 512; CTA g handles batches g and 255-g.
// Warp w owns rows i = 8w..8w+7; lane quad c = lane&3 owns k-chunk [32c,32c+32).
// Whh1 register-resident as f32x2 pairs (96 regs). Register budget trimmed to
// ~121: gi loaded at step START (consumed ~400cyc later at finalize -> latency
// hidden, only 3 live regs), u64 h-loads (2-reg temp).
// h buffer padded to HCH=40-float chunks: load addr bank = (8c+2j)%32 ->
// the 4 quad addresses hit DISTINCT banks (was 4-way conflicted at stride 32).
// Quad reduce via 2 shfl.bfly; finalize on c==0 lanes; hs double-buffered ->
// ONE barrier per step.
// ---------------------------------------------------------------------------
__global__ void __launch_bounds__(512, 1) k2_rnn(
    const int* __restrict__ len, const float* __restrict__ h01,
    const float* __restrict__ Whh1, const float* __restrict__ bhh1) {
    __shared__ __align__(16) float hs[2][4 * HCH];   // [buf][c-chunk padded]

    int tid  = threadIdx.x;
    int lane = tid & 31;
    int warp = tid >> 5;
    int i    = warp * 8 + (lane >> 2);   // row (0..127)
    int c    = lane & 3;                  // k-chunk
    bool fin = (c == 0);
    int hslot = (i >> 5) * HCH + (i & 31);   // padded h position for row i

    // Register-resident Whh1 (packed k-pairs): rows {i, 128+i, 256+i}, k in [32c,32c+32)
    u64 wr[16], wz[16], wn[16];
    {
        const float2* W2 = (const float2*)Whh1;
        int rr = i * 64 + c * 16;
        int rz = (128 + i) * 64 + c * 16;
        int rn = (256 + i) * 64 + c * 16;
#pragma unroll
        for (int j = 0; j < 16; j++) {
            float2 a = W2[rr + j]; wr[j] = pack2(a.x, a.y);
            float2 bz2 = W2[rz + j]; wz[j] = pack2(bz2.x, bz2.y);
            float2 bn2 = W2[rn + j]; wn[j] = pack2(bn2.x, bn2.y);
        }
    }
    float bn = bhh1[256 + i];   // only the n-gate hidden bias survives into K2

    for (int half = 0; half < 2; half++) {
        int b = half ? (255 - (int)blockIdx.x) : (int)blockIdx.x;
        int L = len[b];

        float hcur = 0.f;
        if (fin) { hcur = h01[b * H_ + i]; hs[0][hslot] = hcur; }

        const float* gp = g_gi + (size_t)b * T_ * G3 + i;   // gi row t (incrementing)
        float*       op = g_out1 + (size_t)b * T_ * H_ + i; // out1 row t
        __syncthreads();

        for (int t = 0; t < L; t++) {
            const float* hb = hs[t & 1];

            // issue THIS step's gi loads now; consumed at finalize (~400cyc later)
            float gr = 0.f, gz = 0.f, gn = 0.f;
            if (fin) { gr = gp[0]; gz = gp[128]; gn = gp[256]; }
            gp += G3;

            // matvec partials over k-chunk c — conflict-free u64 h loads
            u64 Z = pack2(0.f, 0.f);
            u64 ar = Z, az = Z, an = Z;
            const u64* hb8 = (const u64*)(hb + c * HCH);
#pragma unroll
            for (int j = 0; j < 16; j++) {
                u64 hv = hb8[j];
                ar = fma2(wr[j], hv, ar);
                az = fma2(wz[j], hv, az);
                an = fma2(wn[j], hv, an);
            }

            // horizontal + quad reduction
            float sr, sz, sn;
            {
                float lo, hi;
                unpack2(ar, lo, hi); sr = lo + hi;
                unpack2(az, lo, hi); sz = lo + hi;
                unpack2(an, lo, hi); sn = lo + hi;
            }
            sr += __shfl_xor_sync(0xffffffffu, sr, 1);
            sz += __shfl_xor_sync(0xffffffffu, sz, 1);
            sn += __shfl_xor_sync(0xffffffffu, sn, 1);
            sr += __shfl_xor_sync(0xffffffffu, sr, 2);
            sz += __shfl_xor_sync(0xffffffffu, sz, 2);
            sn += __shfl_xor_sync(0xffffffffu, sn, 2);

            if (fin) {
                float r = sigm(gr + sr);               // biases pre-folded in K1
                float z = sigm(gz + sz);
                float n = tanh_fast(gn + r * (bn + sn));
                hcur = (1.0f - z) * n + z * hcur;
                hs[(t + 1) & 1][hslot] = hcur;
                *op = hcur;
            }
            op += H_;
            __syncthreads();
        }

        // zero-pad out1 tail
        {
            size_t obase = ((size_t)b * T_ + L) * H_;
            int cnt = (T_ - L) * H_;
            for (int idx = tid; idx < cnt; idx += 512) g_out1[obase + idx] = 0.f;
        }
        __syncthreads();
    }
}

// ---------------------------------------------------------------------------
// K3 (+ fused GRU2 input projection, replacing the standalone k2s kernel):
// preds[b,t,c] = bfc[c] + sum_k out1[b,t,k]*Wfc[c,k] + x[b,t,0]*Wfc[c,128]
//   for t < len[b]-1; 0 elsewhere.
// s[t][g][b]  = bih2[g] + sum_k out1[b,t,k]*Wih2[g,k]  for all t < len[b]
//   (the h-tile is already in smem; +1.5 small dots per thread).
// grid (8, 256), block 128. Tiles with t0 >= L: pure zero. Tiles with
// L1 <= t0 < L (t0 == L-1): compute s only, zero preds.
// ---------------------------------------------------------------------------
__global__ void __launch_bounds__(128) k3_fc(
    const float* __restrict__ x, const int* __restrict__ len,
    const float* __restrict__ Wih2, const float* __restrict__ bih2,
    const float* __restrict__ bfc, float* __restrict__ preds) {
    int b = blockIdx.y, t0 = blockIdx.x * TT, tid = threadIdx.x;
    int L = len[b];
    int L1 = L - 1;

    if (t0 >= L) {  // fully dead tile: exact zeros (d_out is poisoned)
        for (int tt = 0; tt < TT; tt++) {
            int t = t0 + tt;
            if (t >= T_ - 1) break;
            preds[((size_t)b * (T_ - 1) + t) * H_ + tid] = 0.f;
        }
        return;
    }

    __shared__ __align__(16) float hsm[Cp1 * TTPAD];   // [k][tt], k=128 is time feature
    {
        int w = tid >> 5, l = tid & 31;
        for (int tt = w; tt < TT; tt += 4) {
            int t = t0 + tt;
            const float* hr = g_out1 + ((size_t)b * T_ + t) * H_;   // zero-padded for t>=L
            for (int k = l; k < H_; k += 32) hsm[k * TTPAD + tt] = hr[k];
            if (l == 0) hsm[128 * TTPAD + tt] = x[((size_t)b * T_ + t) * Cp1];
        }
    }
    __syncthreads();

    // --- fused GRU2 input projections for t in [t0, min(t0+32, L)) ---
    {
        int smax = (L - t0 < TT) ? (L - t0) : TT;
        int g = tid >> 5, tt = tid & 31;            // gates 0..3
        if (tt < smax) {
            float acc = bih2[g];
            const float* Wg = Wih2 + g * H_;
#pragma unroll 8
            for (int k = 0; k < H_; k++) acc += __ldg(Wg + k) * hsm[k * TTPAD + tt];
            g_s[(size_t)(t0 + tt) * (6 * B_) + g * B_ + b] = acc;
        }
        if (tid < 64) {                              // gates 4..5
            int g2 = 4 + (tid >> 5), tt2 = tid & 31;
            if (tt2 < smax) {
                float acc = bih2[g2];
                const float* Wg = Wih2 + g2 * H_;
#pragma unroll 8
                for (int k = 0; k < H_; k++) acc += __ldg(Wg + k) * hsm[k * TTPAD + tt2];
                g_s[(size_t)(t0 + tt2) * (6 * B_) + g2 * B_ + b] = acc;
            }
        }
    }

    if (t0 >= L1) {  // only s was needed from this tile; preds fully masked
        for (int tt = 0; tt < TT; tt++) {
            int t = t0 + tt;
            if (t >= T_ - 1) break;
            preds[((size_t)b * (T_ - 1) + t) * H_ + tid] = 0.f;
        }
        return;
    }

    float bb = bfc[tid];
    u64 acc[16];
#pragma unroll
    for (int j = 0; j < 16; j++) acc[j] = pack2(bb, bb);

    const float* WT = g_WfcT;
    for (int k = 0; k < Cp1; k++) {
        float w = __ldg(WT + k * H_ + tid);
        u64 wp = pack2(w, w);
        const ulonglong2* hs16 = (const ulonglong2*)(hsm + k * TTPAD);
#pragma unroll
        for (int j = 0; j < 8; j++) {
            ulonglong2 hv = hs16[j];
            acc[2 * j]     = fma2(wp, hv.x, acc[2 * j]);
            acc[2 * j + 1] = fma2(wp, hv.y, acc[2 * j + 1]);
        }
    }

#pragma unroll
    for (int j = 0; j < 16; j++) {
        float lo, hi;
        unpack2(acc[j], lo, hi);
        int t = t0 + 2 * j;
        if (t < T_ - 1) preds[((size_t)b * (T_ - 1) + t) * H_ + tid] = (t < L1) ? lo : 0.f;
        t++;
        if (t < T_ - 1) preds[((size_t)b * (T_ - 1) + t) * H_ + tid] = (t < L1) ? hi : 0.f;
    }
}

// ---------------------------------------------------------------------------
// K2c: GRU2 P=2 recurrence + params = exp(-h2). One lane per batch,
// grid 8 x 32 threads, no barriers, 3-deep s-prefetch hides L2 latency.
// Tail t >= L: params = exp(-0) = 1. Runs AFTER K3 (which produces g_s).
// ---------------------------------------------------------------------------
__global__ void k2c_scan(const int* __restrict__ len, const float* __restrict__ h02,
                         const float* __restrict__ Whh2, const float* __restrict__ bhh2,
                         float* __restrict__ params) {
    int b = blockIdx.x * 32 + threadIdx.x;
    int L = len[b];
    float h2a = h02[b * 2], h2b = h02[b * 2 + 1];
    float wq[12], bq[6];
#pragma unroll
    for (int q = 0; q < 12; q++) wq[q] = Whh2[q];
#pragma unroll
    for (int q = 0; q < 6; q++) bq[q] = bhh2[q];

    const float* S = g_s;
    float s0[6], s1[6], s2[6];
#pragma unroll
    for (int g = 0; g < 6; g++) s0[g] = S[(size_t)0 * (6 * B_) + g * B_ + b];
    int t1 = (1 < L) ? 1 : L - 1;
#pragma unroll
    for (int g = 0; g < 6; g++) s1[g] = S[(size_t)t1 * (6 * B_) + g * B_ + b];
    int t2 = (2 < L) ? 2 : L - 1;
#pragma unroll
    for (int g = 0; g < 6; g++) s2[g] = S[(size_t)t2 * (6 * B_) + g * B_ + b];

    for (int t = 0; t < L; t++) {
        float gh[6];
#pragma unroll
        for (int q = 0; q < 6; q++) gh[q] = bq[q] + wq[2 * q] * h2a + wq[2 * q + 1] * h2b;
        float r0 = sigm(s0[0] + gh[0]);
        float r1 = sigm(s0[1] + gh[1]);
        float z0 = sigm(s0[2] + gh[2]);
        float z1 = sigm(s0[3] + gh[3]);
        float n0 = tanh_fast(s0[4] + r0 * gh[4]);
        float n1 = tanh_fast(s0[5] + r1 * gh[5]);
        h2a = (1.0f - z0) * n0 + z0 * h2a;
        h2b = (1.0f - z1) * n1 + z1 * h2b;
        size_t o = ((size_t)b * T_ + t) * 2;
        params[o]     = __expf(-h2a);
        params[o + 1] = __expf(-h2b);

#pragma unroll
        for (int g = 0; g < 6; g++) { s0[g] = s1[g]; s1[g] = s2[g]; }
        int tn = (t + 3 < L) ? t + 3 : L - 1;
#pragma unroll
        for (int g = 0; g < 6; g++) s2[g] = S[(size_t)tn * (6 * B_) + g * B_ + b];
    }
    for (int t = L; t < T_; t++) {
        size_t o = ((size_t)b * T_ + t) * 2;
        params[o] = 1.0f;
        params[o + 1] = 1.0f;
    }
}

// ---------------------------------------------------------------------------
extern "C" void kernel_launch(void* const* d_in, const int* in_sizes, int n_in,
                              void* d_out, int out_size) {
    const float* x    = (const float*)d_in[0];
    const int*   len  = (const int*)  d_in[1];
    const float* h01  = (const float*)d_in[2];
    const float* h02  = (const float*)d_in[3];
    const float* Wih1 = (const float*)d_in[4];
    const float* Whh1 = (const float*)d_in[5];
    const float* bih1 = (const float*)d_in[6];
    const float* bhh1 = (const float*)d_in[7];
    const float* Wih2 = (const float*)d_in[8];
    const float* Whh2 = (const float*)d_in[9];
    const float* bih2 = (const float*)d_in[10];
    const float* bhh2 = (const float*)d_in[11];
    const float* Wfc  = (const float*)d_in[12];
    const float* bfc  = (const float*)d_in[13];

    float* preds  = (float*)d_out;                              // (B, T-1, C)
    float* params = preds + (size_t)B_ * (T_ - 1) * H_;         // (B, T, 2)
    float* olen   = params + (size_t)B_ * T_ * 2;               // (B,)

    k0_transpose<<<(Cp1 * G3 + 255) / 256, 256>>>(Wih1, Wfc);
    k1_gi<<<dim3(8, B_), 384>>>(x, len, bih1, bhh1, olen);
    k2_rnn<<<128, 512>>>(len, h01, Whh1, bhh1);
    k3_fc<<<dim3(8, B_), 128>>>(x, len, Wih2, bih2, bfc, preds);
    k2c_scan<<<8, 32>>>(len, h02, Whh2, bhh2, params);
}

// round 17
// speedup vs baseline: 1.4742x; 1.0839x over previous
#include <cuda_runtime.h>

#define B_   256
#define T_   256
#define Cp1  129
#define H_   128
#define G3   384
#define TT   32
#define TTPAD 36
#define HCH  40   // padded h-chunk stride (floats) in K2: bank offset 8c -> conflict-free

// Scratch (static __device__ arrays — no runtime allocation)
__device__ float g_gi[(size_t)B_ * T_ * G3];     // (B, T, 3H) GRU1 input proj incl. bih1 (+bhh1 r/z)
__device__ float g_out1[(size_t)B_ * T_ * H_];   // (B, T, H) zero-padded GRU1 output
__device__ float g_WihT[Cp1 * G3];               // transposed Wih1: [k][g]
__device__ float g_WfcT[Cp1 * H_];               // transposed Wfc:  [k][c]
__device__ float g_s[(size_t)T_ * 6 * B_];       // GRU2 input projections: [t][gate][b]

typedef unsigned long long u64;

__device__ __forceinline__ u64 pack2(float lo, float hi) {
    u64 r;
    asm("mov.b64 %0, {%1, %2};" : "=l"(r) : "r"(__float_as_uint(lo)), "r"(__float_as_uint(hi)));
    return r;
}
__device__ __forceinline__ void unpack2(u64 v, float& lo, float& hi) {
    unsigned int a, b;
    asm("mov.b64 {%0, %1}, %2;" : "=r"(a), "=r"(b) : "l"(v));
    lo = __uint_as_float(a); hi = __uint_as_float(b);
}
__device__ __forceinline__ u64 fma2(u64 a, u64 b, u64 c) {
    u64 d;
    asm("fma.rn.f32x2 %0, %1, %2, %3;" : "=l"(d) : "l"(a), "l"(b), "l"(c));
    return d;
}
// Fast activations: MUFU-based (measured total rel_err 2.9e-7, threshold 1e-3).
__device__ __forceinline__ float sigm(float v) {
    return __fdividef(1.0f, 1.0f + __expf(-v));
}
__device__ __forceinline__ float tanh_fast(float x) {
    float t = __expf(-2.0f * fabsf(x));            // in (0, 1]: overflow-safe
    float r = (1.0f - t) * __fdividef(1.0f, 1.0f + t);
    return copysignf(r, x);
}

// ---------------------------------------------------------------------------
// K0: one-off weight transposes so K1/K3 weight loads are fully coalesced.
// ---------------------------------------------------------------------------
__global__ void k0_transpose(const float* __restrict__ Wih1, const float* __restrict__ Wfc) {
    int idx = blockIdx.x * 256 + threadIdx.x;
    if (idx < Cp1 * G3) {
        int k = idx / G3, g = idx - k * G3;
        g_WihT[idx] = Wih1[(size_t)g * Cp1 + k];
    }
    if (idx < Cp1 * H_) {
        int k = idx / H_, c = idx - k * H_;
        g_WfcT[idx] = Wfc[(size_t)c * Cp1 + k];
    }
}

// ---------------------------------------------------------------------------
// K1: gi[b,t,g] = bih1[g] (+ bhh1[g] for r/z gates) + sum_d x[b,t,d]*Wih1[g,d].
// block 384, ONE gate-row per thread (16 u64 accs = 32 regs, no spills).
// k-loop unrolled x4 -> 4 independent weight LDGs in flight (MLP).
// grid (8, 256). Also writes lengths (as float) to the output tail.
// ---------------------------------------------------------------------------
__global__ void __launch_bounds__(384) k1_gi(
    const float* __restrict__ x, const int* __restrict__ len,
    const float* __restrict__ bih1, const float* __restrict__ bhh1,
    float* __restrict__ olen) {
    int b = blockIdx.y, t0 = blockIdx.x * TT, tid = threadIdx.x;
    int L = len[b];
    if (blockIdx.x == 0 && tid == 0) olen[b] = (float)L;
    if (t0 >= L) return;

    __shared__ __align__(16) float xs[Cp1 * TTPAD];   // [k][tt]
    {
        int w = tid >> 5, l = tid & 31;
        for (int tt = w; tt < TT; tt += 12) {
            const float* xrow = x + ((size_t)b * T_ + t0 + tt) * Cp1;
            for (int k = l; k < Cp1; k += 32) xs[k * TTPAD + tt] = xrow[k];
        }
    }
    __syncthreads();

    int g = tid;                                   // gate-row 0..383
    float bb = bih1[g] + ((g < 256) ? bhh1[g] : 0.0f);  // fold r/z hidden biases

    u64 a[16];
#pragma unroll
    for (int j = 0; j < 16; j++) a[j] = pack2(bb, bb);

    const float* WT = g_WihT;
#pragma unroll 4
    for (int k = 0; k < Cp1; k++) {
        float w = __ldg(WT + k * G3 + g);          // coalesced across 384 threads
        u64 wp = pack2(w, w);
        const ulonglong2* xs16 = (const ulonglong2*)(xs + k * TTPAD);  // broadcast
#pragma unroll
        for (int j = 0; j < 8; j++) {
            ulonglong2 xv = xs16[j];
            a[2 * j]     = fma2(wp, xv.x, a[2 * j]);
            a[2 * j + 1] = fma2(wp, xv.y, a[2 * j + 1]);
        }
    }

    size_t base = ((size_t)b * T_ + t0) * G3;
#pragma unroll
    for (int j = 0; j < 16; j++) {
        float lo, hi;
        unpack2(a[j], lo, hi);
        g_gi[base + (size_t)(2 * j) * G3 + g] = lo;
        g_gi[base + (size_t)(2 * j + 1) * G3 + g] = hi;
    }
}

// ---------------------------------------------------------------------------
// K2: GRU1 recurrence. grid 128, block 512; CTA g handles batches g and 255-g.
// Warp w owns rows i = 8w..8w+7; lane quad c = lane&3 owns k-chunk [32c,32c+32).
// Whh1 register-resident as f32x2 pairs (96 regs).
// gi PIPELINE: quad lanes c=1/2/3 each load ONE gate's gi for step t+1 while
// step t computes (one full step of latency hiding, 2 regs total); values
// reach the c=0 finalize lane via 3 shfl.sync. h buffer padded to HCH=40
// chunks -> conflict-free LDS. Quad reduce via 2 shfl.bfly; hs
// double-buffered -> ONE barrier per step.
// ---------------------------------------------------------------------------
__global__ void __launch_bounds__(512, 1) k2_rnn(
    const int* __restrict__ len, const float* __restrict__ h01,
    const float* __restrict__ Whh1, const float* __restrict__ bhh1) {
    __shared__ __align__(16) float hs[2][4 * HCH];   // [buf][c-chunk padded]

    int tid  = threadIdx.x;
    int lane = tid & 31;
    int warp = tid >> 5;
    int i    = warp * 8 + (lane >> 2);   // row (0..127)
    int c    = lane & 3;                  // k-chunk / gi role
    bool fin = (c == 0);
    int qbase = lane & ~3;                // quad leader lane
    int hslot = (i >> 5) * HCH + (i & 31);

    // Register-resident Whh1 (packed k-pairs): rows {i, 128+i, 256+i}, k in [32c,32c+32)
    u64 wr[16], wz[16], wn[16];
    {
        const float2* W2 = (const float2*)Whh1;
        int rr = i * 64 + c * 16;
        int rz = (128 + i) * 64 + c * 16;
        int rn = (256 + i) * 64 + c * 16;
#pragma unroll
        for (int j = 0; j < 16; j++) {
            float2 a = W2[rr + j]; wr[j] = pack2(a.x, a.y);
            float2 bz2 = W2[rz + j]; wz[j] = pack2(bz2.x, bz2.y);
            float2 bn2 = W2[rn + j]; wn[j] = pack2(bn2.x, bn2.y);
        }
    }
    float bn = bhh1[256 + i];   // only the n-gate hidden bias survives into K2

    for (int half = 0; half < 2; half++) {
        int b = half ? (255 - (int)blockIdx.x) : (int)blockIdx.x;
        int L = len[b];

        float hcur = 0.f;
        if (fin) { hcur = h01[b * H_ + i]; hs[0][hslot] = hcur; }

        // gi role pointer: lane c>0 tracks gate (c-1) of row i.
        const float* gp = g_gi + (size_t)b * T_ * G3 + i + (c > 0 ? (c - 1) * H_ : 0);
        float*       op = g_out1 + (size_t)b * T_ * H_ + i;

        float gcur = (c > 0) ? gp[0] : 0.f;   // gi for t=0
        __syncthreads();

        for (int t = 0; t < L; t++) {
            const float* hb = hs[t & 1];

            // prefetch gi for t+1 (clamped pointer: re-reads row L-1 harmlessly)
            if (t + 1 < L) gp += G3;
            float gnxt = (c > 0) ? gp[0] : 0.f;

            // matvec partials over k-chunk c — conflict-free u64 h loads
            u64 Z = pack2(0.f, 0.f);
            u64 ar = Z, az = Z, an = Z;
            const u64* hb8 = (const u64*)(hb + c * HCH);
#pragma unroll
            for (int j = 0; j < 16; j++) {
                u64 hv = hb8[j];
                ar = fma2(wr[j], hv, ar);
                az = fma2(wz[j], hv, az);
                an = fma2(wn[j], hv, an);
            }

            // horizontal + quad reduction
            float sr, sz, sn;
            {
                float lo, hi;
                unpack2(ar, lo, hi); sr = lo + hi;
                unpack2(az, lo, hi); sz = lo + hi;
                unpack2(an, lo, hi); sn = lo + hi;
            }
            sr += __shfl_xor_sync(0xffffffffu, sr, 1);
            sz += __shfl_xor_sync(0xffffffffu, sz, 1);
            sn += __shfl_xor_sync(0xffffffffu, sn, 1);
            sr += __shfl_xor_sync(0xffffffffu, sr, 2);
            sz += __shfl_xor_sync(0xffffffffu, sz, 2);
            sn += __shfl_xor_sync(0xffffffffu, sn, 2);

            // gather this step's gi (loaded one step ago) to the finalize lane
            float gr = __shfl_sync(0xffffffffu, gcur, qbase + 1);
            float gz = __shfl_sync(0xffffffffu, gcur, qbase + 2);
            float gn = __shfl_sync(0xffffffffu, gcur, qbase + 3);

            if (fin) {
                float r = sigm(gr + sr);               // r/z biases pre-folded in K1
                float z = sigm(gz + sz);
                float n = tanh_fast(gn + r * (bn + sn));
                hcur = (1.0f - z) * n + z * hcur;
                hs[(t + 1) & 1][hslot] = hcur;
                *op = hcur;
            }
            gcur = gnxt;
            op += H_;
            __syncthreads();
        }

        // zero-pad out1 tail
        {
            size_t obase = ((size_t)b * T_ + L) * H_;
            int cnt = (T_ - L) * H_;
            for (int idx = tid; idx < cnt; idx += 512) g_out1[obase + idx] = 0.f;
        }
        __syncthreads();
    }
}

// ---------------------------------------------------------------------------
// K3 (+ fused GRU2 input projection):
// preds[b,t,c] = bfc[c] + sum_k out1[b,t,k]*Wfc[c,k] + x[b,t,0]*Wfc[c,128]
//   for t < len[b]-1; 0 elsewhere.
// s[t][g][b]  = bih2[g] + sum_k out1[b,t,k]*Wih2[g,k]  for all t < len[b].
// grid (8, 256), block 128. k-loop unrolled x4 for weight-LDG MLP.
// ---------------------------------------------------------------------------
__global__ void __launch_bounds__(128) k3_fc(
    const float* __restrict__ x, const int* __restrict__ len,
    const float* __restrict__ Wih2, const float* __restrict__ bih2,
    const float* __restrict__ bfc, float* __restrict__ preds) {
    int b = blockIdx.y, t0 = blockIdx.x * TT, tid = threadIdx.x;
    int L = len[b];
    int L1 = L - 1;

    if (t0 >= L) {  // fully dead tile: exact zeros (d_out is poisoned)
        for (int tt = 0; tt < TT; tt++) {
            int t = t0 + tt;
            if (t >= T_ - 1) break;
            preds[((size_t)b * (T_ - 1) + t) * H_ + tid] = 0.f;
        }
        return;
    }

    __shared__ __align__(16) float hsm[Cp1 * TTPAD];   // [k][tt], k=128 is time feature
    {
        int w = tid >> 5, l = tid & 31;
        for (int tt = w; tt < TT; tt += 4) {
            int t = t0 + tt;
            const float* hr = g_out1 + ((size_t)b * T_ + t) * H_;   // zero-padded for t>=L
            for (int k = l; k < H_; k += 32) hsm[k * TTPAD + tt] = hr[k];
            if (l == 0) hsm[128 * TTPAD + tt] = x[((size_t)b * T_ + t) * Cp1];
        }
    }
    __syncthreads();

    // --- fused GRU2 input projections for t in [t0, min(t0+32, L)) ---
    {
        int smax = (L - t0 < TT) ? (L - t0) : TT;
        int g = tid >> 5, tt = tid & 31;            // gates 0..3
        if (tt < smax) {
            float acc = bih2[g];
            const float* Wg = Wih2 + g * H_;
#pragma unroll 8
            for (int k = 0; k < H_; k++) acc += __ldg(Wg + k) * hsm[k * TTPAD + tt];
            g_s[(size_t)(t0 + tt) * (6 * B_) + g * B_ + b] = acc;
        }
        if (tid < 64) {                              // gates 4..5
            int g2 = 4 + (tid >> 5), tt2 = tid & 31;
            if (tt2 < smax) {
                float acc = bih2[g2];
                const float* Wg = Wih2 + g2 * H_;
#pragma unroll 8
                for (int k = 0; k < H_; k++) acc += __ldg(Wg + k) * hsm[k * TTPAD + tt2];
                g_s[(size_t)(t0 + tt2) * (6 * B_) + g2 * B_ + b] = acc;
            }
        }
    }

    if (t0 >= L1) {  // only s was needed from this tile; preds fully masked
        for (int tt = 0; tt < TT; tt++) {
            int t = t0 + tt;
            if (t >= T_ - 1) break;
            preds[((size_t)b * (T_ - 1) + t) * H_ + tid] = 0.f;
        }
        return;
    }

    float bb = bfc[tid];
    u64 acc[16];
#pragma unroll
    for (int j = 0; j < 16; j++) acc[j] = pack2(bb, bb);

    const float* WT = g_WfcT;
#pragma unroll 4
    for (int k = 0; k < Cp1; k++) {
        float w = __ldg(WT + k * H_ + tid);
        u64 wp = pack2(w, w);
        const ulonglong2* hs16 = (const ulonglong2*)(hsm + k * TTPAD);
#pragma unroll
        for (int j = 0; j < 8; j++) {
            ulonglong2 hv = hs16[j];
            acc[2 * j]     = fma2(wp, hv.x, acc[2 * j]);
            acc[2 * j + 1] = fma2(wp, hv.y, acc[2 * j + 1]);
        }
    }

#pragma unroll
    for (int j = 0; j < 16; j++) {
        float lo, hi;
        unpack2(acc[j], lo, hi);
        int t = t0 + 2 * j;
        if (t < T_ - 1) preds[((size_t)b * (T_ - 1) + t) * H_ + tid] = (t < L1) ? lo : 0.f;
        t++;
        if (t < T_ - 1) preds[((size_t)b * (T_ - 1) + t) * H_ + tid] = (t < L1) ? hi : 0.f;
    }
}

// ---------------------------------------------------------------------------
// K2c: GRU2 P=2 recurrence + params = exp(-h2). One lane per batch,
// grid 8 x 32 threads, no barriers, 3-deep s-prefetch hides L2 latency.
// Tail t >= L: params = exp(-0) = 1. Runs AFTER K3 (which produces g_s).
// ---------------------------------------------------------------------------
__global__ void k2c_scan(const int* __restrict__ len, const float* __restrict__ h02,
                         const float* __restrict__ Whh2, const float* __restrict__ bhh2,
                         float* __restrict__ params) {
    int b = blockIdx.x * 32 + threadIdx.x;
    int L = len[b];
    float h2a = h02[b * 2], h2b = h02[b * 2 + 1];
    float wq[12], bq[6];
#pragma unroll
    for (int q = 0; q < 12; q++) wq[q] = Whh2[q];
#pragma unroll
    for (int q = 0; q < 6; q++) bq[q] = bhh2[q];

    const float* S = g_s;
    float s0[6], s1[6], s2[6];
#pragma unroll
    for (int g = 0; g < 6; g++) s0[g] = S[(size_t)0 * (6 * B_) + g * B_ + b];
    int t1 = (1 < L) ? 1 : L - 1;
#pragma unroll
    for (int g = 0; g < 6; g++) s1[g] = S[(size_t)t1 * (6 * B_) + g * B_ + b];
    int t2 = (2 < L) ? 2 : L - 1;
#pragma unroll
    for (int g = 0; g < 6; g++) s2[g] = S[(size_t)t2 * (6 * B_) + g * B_ + b];

    for (int t = 0; t < L; t++) {
        float gh[6];
#pragma unroll
        for (int q = 0; q < 6; q++) gh[q] = bq[q] + wq[2 * q] * h2a + wq[2 * q + 1] * h2b;
        float r0 = sigm(s0[0] + gh[0]);
        float r1 = sigm(s0[1] + gh[1]);
        float z0 = sigm(s0[2] + gh[2]);
        float z1 = sigm(s0[3] + gh[3]);
        float n0 = tanh_fast(s0[4] + r0 * gh[4]);
        float n1 = tanh_fast(s0[5] + r1 * gh[5]);
        h2a = (1.0f - z0) * n0 + z0 * h2a;
        h2b = (1.0f - z1) * n1 + z1 * h2b;
        size_t o = ((size_t)b * T_ + t) * 2;
        params[o]     = __expf(-h2a);
        params[o + 1] = __expf(-h2b);

#pragma unroll
        for (int g = 0; g < 6; g++) { s0[g] = s1[g]; s1[g] = s2[g]; }
        int tn = (t + 3 < L) ? t + 3 : L - 1;
#pragma unroll
        for (int g = 0; g < 6; g++) s2[g] = S[(size_t)tn * (6 * B_) + g * B_ + b];
    }
    for (int t = L; t < T_; t++) {
        size_t o = ((size_t)b * T_ + t) * 2;
        params[o] = 1.0f;
        params[o + 1] = 1.0f;
    }
}

// ---------------------------------------------------------------------------
extern "C" void kernel_launch(void* const* d_in, const int* in_sizes, int n_in,
                              void* d_out, int out_size) {
    const float* x    = (const float*)d_in[0];
    const int*   len  = (const int*)  d_in[1];
    const float* h01  = (const float*)d_in[2];
    const float* h02  = (const float*)d_in[3];
    const float* Wih1 = (const float*)d_in[4];
    const float* Whh1 = (const float*)d_in[5];
    const float* bih1 = (const float*)d_in[6];
    const float* bhh1 = (const float*)d_in[7];
    const float* Wih2 = (const float*)d_in[8];
    const float* Whh2 = (const float*)d_in[9];
    const float* bih2 = (const float*)d_in[10];
    const float* bhh2 = (const float*)d_in[11];
    const float* Wfc  = (const float*)d_in[12];
    const float* bfc  = (const float*)d_in[13];

    float* preds  = (float*)d_out;                              // (B, T-1, C)
    float* params = preds + (size_t)B_ * (T_ - 1) * H_;         // (B, T, 2)
    float* olen   = params + (size_t)B_ * T_ * 2;               // (B,)

    k0_transpose<<<(Cp1 * G3 + 255) / 256, 256>>>(Wih1, Wfc);
    k1_gi<<<dim3(8, B_), 384>>>(x, len, bih1, bhh1, olen);
    k2_rnn<<<128, 512>>>(len, h01, Whh1, bhh1);
    k3_fc<<<dim3(8, B_), 128>>>(x, len, Wih2, bih2, bfc, preds);
    k2c_scan<<<8, 32>>>(len, h02, Whh2, bhh2, params);
}